// round 7
// baseline (speedup 1.0000x reference)
#include <cuda_runtime.h>
#include <cstdint>
#include <cstddef>

#define N_TOK 4096
#define HDIM  1024
#define NE    8
#define CAP   1536

// ---------------- scratch (static device globals: no allocation) ----------------
// X and Wt stored tf32-split AND k-permuted within each 8-group: order [0,4,1,5,2,6,3,7]
__device__ float g_xhi[(size_t)N_TOK * HDIM];
__device__ float g_xlo[(size_t)N_TOK * HDIM];
__device__ float g_wthi[(size_t)2560 * HDIM];   // [wi1t(512) | wr1t(1024) | wu1t(1024)] rows n, cols k
__device__ float g_wtlo[(size_t)2560 * HDIM];
__device__ float g_hi[(size_t)N_TOK * 512];
__device__ float g_hr[(size_t)N_TOK * 1024];
__device__ float g_p0[N_TOK], g_p1[N_TOK];
__device__ int   g_e0[N_TOK], g_e1[N_TOK];
__device__ unsigned char g_mask[N_TOK];
__device__ int   g_idx_i[N_TOK], g_idx_u[N_TOK];
__device__ int   g_cnt[2];
__device__ float g_part[512 * 16];

// ================= helpers =================
static __device__ __forceinline__ uint32_t smem_u32(const void* p) {
    uint32_t a;
    asm("{ .reg .u64 t; cvta.to.shared.u64 t, %1; cvt.u32.u64 %0, t; }" : "=r"(a) : "l"(p));
    return a;
}
static __device__ __forceinline__ void cp_async16(uint32_t dst, const void* src) {
    asm volatile("cp.async.cg.shared.global [%0], [%1], 16;" :: "r"(dst), "l"(src));
}
static __device__ __forceinline__ void cp_commit() { asm volatile("cp.async.commit_group;" ::: "memory"); }
static __device__ __forceinline__ void cp_wait1()  { asm volatile("cp.async.wait_group 1;"  ::: "memory"); }
static __device__ __forceinline__ void cp_wait0()  { asm volatile("cp.async.wait_group 0;"  ::: "memory"); }

static __device__ __forceinline__ void tf32_split(float v, float& hi, float& lo) {
    uint32_t h;
    asm("cvt.rna.tf32.f32 %0, %1;" : "=r"(h) : "f"(v));
    hi = __uint_as_float(h);
    const float r = v - hi;
    uint32_t l;
    asm("cvt.rna.tf32.f32 %0, %1;" : "=r"(l) : "f"(r));
    lo = __uint_as_float(l);
}

// k-permutation within each 8-group: k -> (k&~7) | ((k&3)<<1) | ((k>>2)&1)
static __device__ __forceinline__ int kperm(int k) {
    return (k & ~7) | (((k & 3) << 1) | ((k >> 2) & 1));
}

// m16n8k8 tf32 mma
static __device__ __forceinline__ void mma8(float4& d, float2 a02, float2 a13, float2 b) {
    asm volatile(
        "mma.sync.aligned.m16n8k8.row.col.f32.tf32.tf32.f32 "
        "{%0,%1,%2,%3}, {%4,%5,%6,%7}, {%8,%9}, {%0,%1,%2,%3};"
        : "+f"(d.x), "+f"(d.y), "+f"(d.z), "+f"(d.w)
        : "r"(__float_as_uint(a02.x)), "r"(__float_as_uint(a13.x)),
          "r"(__float_as_uint(a02.y)), "r"(__float_as_uint(a13.y)),
          "r"(__float_as_uint(b.x)),   "r"(__float_as_uint(b.y)));
}

// ================= mma GEMM core =================
// CTA tile M_TILE x 256, K=1024 in 32 stages of K=32; 2-buffer cp.async pipeline.
// NWARP_M warps along M, 4 along N (64 cols each); warp tile = 32 x 64 (MT=2).
// Stage smem layout (floats): [Ahi A_F][Alo A_F][Bhi 8192][Blo 8192],
// each region holds 4 k8 sub-chunks: sub c at c*(rows*8), row r at r*8 (k-permuted).
template <int M_TILE, int NWARP_M>
__device__ __forceinline__ void gemm_mma_tile(
    const int* __restrict__ tok_list, int row_base, int row_cnt,
    const float* __restrict__ bthi, const float* __restrict__ btlo,
    int ncol0, const float* __restrict__ bias,
    float* __restrict__ outp, int out_ld)
{
    constexpr int NTHR   = NWARP_M * 4 * 32;
    constexpr int A_F    = M_TILE * 32;
    constexpr int B_F    = 256 * 32;             // 8192
    constexpr int STG_F  = 2 * A_F + 2 * B_F;
    constexpr int NP_A   = A_F / 4 / NTHR;
    constexpr int NP_B   = B_F / 4 / NTHR;
    constexpr int MT     = 2;                    // warp covers 32 rows

    extern __shared__ __align__(16) float smem[];
    int* s_tok = (int*)smem;
    float* stg = smem + 128;
    const int tid = threadIdx.x;
    const int wid = tid >> 5, lane = tid & 31;

    if (tid < M_TILE) {
        const int r = row_base + tid;
        s_tok[tid] = tok_list ? ((r < row_cnt) ? tok_list[r] : -1) : r;
    }
    __syncthreads();

    // ---- per-thread cp.async source pointers / dest offsets ----
    const uint32_t sbase = smem_u32(stg);
    const float* srcAh[NP_A]; const float* srcAl[NP_A]; uint32_t dstA[NP_A];
#pragma unroll
    for (int p = 0; p < NP_A; p++) {
        const int i = tid + p * NTHR;
        const int r = i >> 3, j = i & 7;
        const int c = j >> 1, h = j & 1;
        int tok = s_tok[r]; if (tok < 0) tok = 0;
        srcAh[p] = g_xhi + (size_t)tok * HDIM + c * 8 + h * 4;
        srcAl[p] = g_xlo + (size_t)tok * HDIM + c * 8 + h * 4;
        dstA[p]  = (uint32_t)(c * (M_TILE * 8) + r * 8 + h * 4) * 4;
    }
    const float* srcBh[NP_B]; const float* srcBl[NP_B]; uint32_t dstB[NP_B];
#pragma unroll
    for (int p = 0; p < NP_B; p++) {
        const int i = tid + p * NTHR;
        const int r = i >> 3, j = i & 7;
        const int c = j >> 1, h = j & 1;
        srcBh[p] = bthi + (size_t)(ncol0 + r) * HDIM + c * 8 + h * 4;
        srcBl[p] = btlo + (size_t)(ncol0 + r) * HDIM + c * 8 + h * 4;
        dstB[p]  = (uint32_t)(c * (256 * 8) + r * 8 + h * 4) * 4;
    }

    #define ISSUE_STAGE(s) do { \
        const uint32_t _sb = sbase + ((s) & 1) * (STG_F * 4); \
        const int _k = (s) * 32; \
        _Pragma("unroll") \
        for (int p = 0; p < NP_A; p++) { \
            cp_async16(_sb + dstA[p],             srcAh[p] + _k); \
            cp_async16(_sb + A_F * 4 + dstA[p],   srcAl[p] + _k); \
        } \
        _Pragma("unroll") \
        for (int p = 0; p < NP_B; p++) { \
            cp_async16(_sb + 2 * A_F * 4 + dstB[p],           srcBh[p] + _k); \
            cp_async16(_sb + (2 * A_F + B_F) * 4 + dstB[p],   srcBl[p] + _k); \
        } \
        cp_commit(); \
    } while (0)

    float4 acc[MT][8];
#pragma unroll
    for (int mt = 0; mt < MT; mt++)
#pragma unroll
        for (int nt = 0; nt < 8; nt++) acc[mt][nt] = make_float4(0.f, 0.f, 0.f, 0.f);

    const int warpM = (wid & (NWARP_M - 1)) * 32;
    const int warpN = (wid / NWARP_M) * 64;
    const int g = lane >> 2, c = lane & 3;

    ISSUE_STAGE(0);
    ISSUE_STAGE(1);

    for (int s = 0; s < 32; s++) {
        if (s >= 30) cp_wait0(); else cp_wait1();
        __syncthreads();

        const float* sb = stg + (s & 1) * STG_F;
#pragma unroll
        for (int c4 = 0; c4 < 4; c4++) {
            const float* sA = sb + c4 * (M_TILE * 8);
            const float* sB = sb + 2 * A_F + c4 * (256 * 8);
            float2 ah02[MT], ah13[MT], al02[MT], al13[MT];
#pragma unroll
            for (int mt = 0; mt < MT; mt++) {
                const int rbase = (warpM + mt * 16 + g) * 8 + c * 2;
                ah02[mt] = *(const float2*)(sA + rbase);
                ah13[mt] = *(const float2*)(sA + rbase + 64);
                al02[mt] = *(const float2*)(sA + A_F + rbase);
                al13[mt] = *(const float2*)(sA + A_F + rbase + 64);
            }
#pragma unroll
            for (int nt = 0; nt < 8; nt++) {
                const int bbase = (warpN + nt * 8 + g) * 8 + c * 2;
                const float2 bh = *(const float2*)(sB + bbase);
                const float2 bl = *(const float2*)(sB + B_F + bbase);
#pragma unroll
                for (int mt = 0; mt < MT; mt++) {
                    mma8(acc[mt][nt], ah02[mt], ah13[mt], bh);
                    mma8(acc[mt][nt], ah02[mt], ah13[mt], bl);
                    mma8(acc[mt][nt], al02[mt], al13[mt], bh);
                }
            }
        }
        __syncthreads();
        if (s + 2 < 32) ISSUE_STAGE(s + 2);
    }
    #undef ISSUE_STAGE

    // ---- epilogue: bias + relu, float2 stores ----
#pragma unroll
    for (int mt = 0; mt < MT; mt++) {
        const int rr0 = warpM + mt * 16 + g;
        const int rr1 = rr0 + 8;
        const int tok0 = s_tok[rr0];
        const int tok1 = s_tok[rr1];
#pragma unroll
        for (int nt = 0; nt < 8; nt++) {
            const int col = ncol0 + warpN + nt * 8 + c * 2;
            const float2 bs = *(const float2*)(bias + col);
            if (tok0 >= 0) {
                float2 v;
                v.x = fmaxf(acc[mt][nt].x + bs.x, 0.0f);
                v.y = fmaxf(acc[mt][nt].y + bs.y, 0.0f);
                *(float2*)(outp + (size_t)tok0 * out_ld + col) = v;
            }
            if (tok1 >= 0) {
                float2 v;
                v.x = fmaxf(acc[mt][nt].z + bs.x, 0.0f);
                v.y = fmaxf(acc[mt][nt].w + bs.y, 0.0f);
                *(float2*)(outp + (size_t)tok1 * out_ld + col) = v;
            }
        }
    }
}

#define STG_F_64  (2 * 64 * 32 + 2 * 8192)    // 20480 floats
#define STG_F_128 (2 * 128 * 32 + 2 * 8192)   // 24576 floats
#define SMEM_A_TC (512 + 2 * STG_F_64 * 4)    // 164352 B
#define SMEM_C_TC (512 + 2 * STG_F_128 * 4)   // 197120 B

// zeroing split: total output region 25,165,824 float4; each gemm wave zeroes half
#define ZTOT_F4 25165824
#define ZHALF_F4 12582912

// ================= prep: transforms ONLY (weights transpose/split + X split) =======
__global__ __launch_bounds__(256) void prep_kernel(
    const float* __restrict__ x,
    const float* __restrict__ wi1, const float* __restrict__ wr1, const float* __restrict__ wu1)
{
    const int bx = blockIdx.x;
    const int tid = threadIdx.x;
    if (bx < 2560) {
        __shared__ float s_hi[32][33], s_lo[32][33];
        const int tt = bx;
        const float* W; int NC, rowbase, u;
        if (tt < 512)       { W = wi1; NC = 512;  u = tt;        rowbase = (u >> 5) * 32; }
        else if (tt < 1536) { W = wr1; NC = 1024; u = tt - 512;  rowbase = 512  + (u >> 5) * 32; }
        else                { W = wu1; NC = 1024; u = tt - 1536; rowbase = 1536 + (u >> 5) * 32; }
        const int tk = (u & 31) * 32;
        const int nt = ((u >> 5) * 32) % ((W == wi1) ? 512 : 1024);
        const int tx = tid & 31, ty = tid >> 5;
#pragma unroll
        for (int y4 = 0; y4 < 4; y4++) {
            const int y = ty + y4 * 8;
            const float v = W[(size_t)(tk + y) * NC + nt + tx];
            float hh, ll; tf32_split(v, hh, ll);
            s_hi[y][tx] = hh; s_lo[y][tx] = ll;
        }
        __syncthreads();
#pragma unroll
        for (int y4 = 0; y4 < 4; y4++) {
            const int y = ty + y4 * 8;
            const int kp = kperm(tk + tx);
            g_wthi[(size_t)(rowbase + y) * HDIM + kp] = s_hi[tx][y];
            g_wtlo[(size_t)(rowbase + y) * HDIM + kp] = s_lo[tx][y];
        }
        return;
    }
    // X split with k-permutation: 512 CTAs x 2048 float4
    {
        const int xi = bx - 2560;
        const float4* xs = (const float4*)x;
#pragma unroll
        for (int p = 0; p < 8; p++) {
            const size_t i = (size_t)xi * 2048 + p * 256 + tid;
            const float4 v = xs[i];
            float4 hh, ll;
            tf32_split(v.x, hh.x, ll.x);
            tf32_split(v.y, hh.y, ll.y);
            tf32_split(v.z, hh.z, ll.z);
            tf32_split(v.w, hh.w, ll.w);
            const size_t kf = i * 4;
            const size_t d0 = (kf & ~(size_t)7) + ((kf >> 2) & 1);
            g_xhi[d0] = hh.x; g_xhi[d0 + 2] = hh.y; g_xhi[d0 + 4] = hh.z; g_xhi[d0 + 6] = hh.w;
            g_xlo[d0] = ll.x; g_xlo[d0 + 2] = ll.y; g_xlo[d0 + 4] = ll.z; g_xlo[d0 + 6] = ll.w;
        }
    }
}

// ================= gemmA wave: 128 mma CTAs (M64xN256) + 64 zero CTAs ==============
__global__ __launch_bounds__(256, 1) void gemmA_tc(const float* __restrict__ bi1,
                                                   float4* __restrict__ zero_base) {
    const int bx = blockIdx.x;
    if (bx >= 128) {
        const int z = bx - 128;
        const float4 zz = make_float4(0.f, 0.f, 0.f, 0.f);
        for (size_t i = (size_t)z * 256 + threadIdx.x; i < (size_t)ZHALF_F4; i += (size_t)64 * 256)
            zero_base[i] = zz;
        return;
    }
    const int ncol0 = (bx & 1) * 256;
    const int m0    = (bx >> 1) * 64;
    gemm_mma_tile<64, 2>(nullptr, m0, N_TOK, g_wthi, g_wtlo, ncol0, bi1, g_hi, 512);
}

// ================= gemmC: gathered router GEMM (M128xN256, 512 thr) + zero CTAs ====
__global__ __launch_bounds__(512, 1) void gemmC_tc(const float* __restrict__ br1,
                                                   const float* __restrict__ bu1,
                                                   float4* __restrict__ zero_base) {
    const int ci = g_cnt[0], cu = g_cnt[1];
    const int ti = (ci + 127) >> 7;
    const int tu = (cu + 127) >> 7;
    const int nc = ti + tu;                      // 32..34 compute rows
    const int by = blockIdx.y;
    if (by >= nc) {
        // zero role: (49 - nc) * 4 CTAs cover the second half of the output region
        const int z  = (by - nc) * 4 + blockIdx.x;
        const int nz = (49 - nc) * 4;
        const float4 zz = make_float4(0.f, 0.f, 0.f, 0.f);
        for (size_t i = (size_t)z * 512 + threadIdx.x; i < (size_t)ZHALF_F4; i += (size_t)nz * 512)
            zero_base[(size_t)ZHALF_F4 + i] = zz;
        return;
    }
    const float* bias; const int* list; int base, cnt; size_t wrow;
    if (by < ti) { bias = br1; list = g_idx_i; base = by << 7;        cnt = ci; wrow = 512;  }
    else         { bias = bu1; list = g_idx_u; base = (by - ti) << 7; cnt = cu; wrow = 1536; }
    gemm_mma_tile<128, 4>(list, base, cnt,
                          g_wthi + wrow * HDIM, g_wtlo + wrow * HDIM,
                          blockIdx.x * 256, bias, g_hr, 1024);
}

// ================= importance: dot(g_hi, wi2) + sigmoid gate =======================
__global__ void importance_kernel(const float* __restrict__ wi2, const float* __restrict__ bi2,
                                  float* __restrict__ out_imp) {
    const int gt   = (blockIdx.x * blockDim.x + threadIdx.x) >> 5;
    const int lane = threadIdx.x & 31;
    if (gt >= N_TOK) return;
    const float* hr = g_hi + (size_t)gt * 512;
    float z = 0.0f;
    for (int j = lane; j < 512; j += 32) z = fmaf(hr[j], wi2[j], z);
#pragma unroll
    for (int off = 16; off > 0; off >>= 1) z += __shfl_xor_sync(0xffffffffu, z, off);
    if (lane == 0) {
        z += bi2[0];
        const float sig = 1.0f / (1.0f + expf(-z));
        out_imp[gt] = sig;
        g_mask[gt] = (sig > 0.5f) ? 1 : 0;
    }
}

// ================= compaction ======================================================
__global__ void compact_kernel() {
    __shared__ int wcnt_i[32], wcnt_u[32], wpre_i[32], wpre_u[32];
    __shared__ int base_i, base_u;
    const int tid = threadIdx.x, lane = tid & 31, warp = tid >> 5;
    if (tid == 0) { base_i = 0; base_u = 0; }
    __syncthreads();
    for (int cc = 0; cc < 4; cc++) {
        const int t = cc * 1024 + tid;
        const int m = g_mask[t];
        const unsigned bi = __ballot_sync(0xffffffffu, m);
        const unsigned lt = (1u << lane) - 1u;
        if (lane == 0) { wcnt_i[warp] = __popc(bi); wcnt_u[warp] = 32 - __popc(bi); }
        __syncthreads();
        if (tid == 0) {
            int si = base_i, su = base_u;
            for (int w = 0; w < 32; w++) {
                wpre_i[w] = si; si += wcnt_i[w];
                wpre_u[w] = su; su += wcnt_u[w];
            }
            base_i = si; base_u = su;
        }
        __syncthreads();
        if (m) g_idx_i[wpre_i[warp] + __popc(bi & lt)] = t;
        else   g_idx_u[wpre_u[warp] + __popc(~bi & lt)] = t;
        __syncthreads();
    }
    if (tid == 0) { g_cnt[0] = base_i; g_cnt[1] = base_u; }
}

// ================= routing: layer 2 + softmax + top-2 + aux partials ===============
__global__ void routing_kernel(const float* __restrict__ wr2, const float* __restrict__ br2,
                               const float* __restrict__ wu2, const float* __restrict__ bu2,
                               float* __restrict__ out_probs) {
    __shared__ float s_aux[8][16];
    const int gt   = (blockIdx.x * blockDim.x + threadIdx.x) >> 5;
    const int lane = threadIdx.x & 31;
    const int warp = threadIdx.x >> 5;
    if (gt < N_TOK) {
        const bool m = g_mask[gt] != 0;
        const float* hs = g_hr + (size_t)gt * 1024;
        const float* W2 = m ? wr2 : wu2;
        const float* b2 = m ? br2 : bu2;
        float acc[NE];
#pragma unroll
        for (int e = 0; e < NE; e++) acc[e] = 0.0f;
        for (int j = lane; j < 1024; j += 32) {
            const float hv = hs[j];
            float4 w0 = *(const float4*)(W2 + (size_t)j * 8);
            float4 w1 = *(const float4*)(W2 + (size_t)j * 8 + 4);
            acc[0] = fmaf(hv, w0.x, acc[0]);
            acc[1] = fmaf(hv, w0.y, acc[1]);
            acc[2] = fmaf(hv, w0.z, acc[2]);
            acc[3] = fmaf(hv, w0.w, acc[3]);
            acc[4] = fmaf(hv, w1.x, acc[4]);
            acc[5] = fmaf(hv, w1.y, acc[5]);
            acc[6] = fmaf(hv, w1.z, acc[6]);
            acc[7] = fmaf(hv, w1.w, acc[7]);
        }
#pragma unroll
        for (int off = 16; off > 0; off >>= 1)
#pragma unroll
            for (int e = 0; e < NE; e++) acc[e] += __shfl_xor_sync(0xffffffffu, acc[e], off);

        if (lane == 0) {
            float l[NE], pr[NE];
            float mx = -1e30f;
#pragma unroll
            for (int e = 0; e < NE; e++) { l[e] = acc[e] + b2[e]; mx = fmaxf(mx, l[e]); }
            float sum = 0.0f;
#pragma unroll
            for (int e = 0; e < NE; e++) { pr[e] = expf(l[e] - mx); sum += pr[e]; }
            const float inv = 1.0f / sum;
            const float mf = m ? 1.0f : 0.0f;
#pragma unroll
            for (int e = 0; e < NE; e++) {
                pr[e] *= inv;
                out_probs[(size_t)gt * NE + e] = pr[e];
                s_aux[warp][e]      = pr[e];
                s_aux[warp][NE + e] = pr[e] * mf;
            }
            int e0 = 0; float p0v = pr[0];
#pragma unroll
            for (int e = 1; e < NE; e++) if (pr[e] > p0v) { p0v = pr[e]; e0 = e; }
            int e1 = -1; float p1v = -1.0f;
#pragma unroll
            for (int e = 0; e < NE; e++) if (e != e0 && pr[e] > p1v) { p1v = pr[e]; e1 = e; }
            const float sn = p0v + p1v;
            g_e0[gt] = e0; g_e1[gt] = e1;
            g_p0[gt] = p0v / sn; g_p1[gt] = p1v / sn;
        }
    }
    __syncthreads();
    if (threadIdx.x < 16) {
        float s = 0.0f;
        for (int w = 0; w < 8; w++) s += s_aux[w][threadIdx.x];
        g_part[(size_t)blockIdx.x * 16 + threadIdx.x] = s;
    }
}

// ================= dispatch (block 0) + aux loss (block 1) =========================
__global__ void dispatch_aux_kernel(float* __restrict__ disp, float* __restrict__ comb,
                                    float* __restrict__ out_aux) {
    const int tid = threadIdx.x;
    if (blockIdx.x == 0) {
        __shared__ int base[NE];
        __shared__ int whist[32][NE];
        __shared__ int wpref[32][NE];
        const int lane = tid & 31, warp = tid >> 5;
        if (tid < NE) base[tid] = 0;
        __syncthreads();
        for (int chunk = 0; chunk < 8; chunk++) {
            const int i = chunk * 1024 + tid;
            const int k = i >> 12;
            const int t = i & (N_TOK - 1);
            const int e   = (k == 0) ? g_e0[t] : g_e1[t];
            const float p = (k == 0) ? g_p0[t] : g_p1[t];

            if (lane < NE) whist[warp][lane] = 0;
            __syncwarp();
            const unsigned mm  = __match_any_sync(0xffffffffu, e);
            const unsigned blo = mm & ((1u << lane) - 1u);
            const int rank = __popc(blo);
            if (blo == 0u) whist[warp][e] = __popc(mm);
            __syncthreads();

            if (tid < NE) {
                int s = base[tid];
                for (int w = 0; w < 32; w++) { wpref[w][tid] = s; s += whist[w][tid]; }
                base[tid] = s;
            }
            __syncthreads();

            const int pos = wpref[warp][e] + rank;
            if (pos < CAP) {
                const size_t idx = ((size_t)t * NE + e) * CAP + pos;
                disp[idx] = 1.0f;
                comb[idx] = p;
            }
            __syncthreads();
        }
    } else {
        __shared__ float sm[512][16];
        if (tid < 512) {
#pragma unroll
            for (int v = 0; v < 16; v++) sm[tid][v] = g_part[(size_t)tid * 16 + v];
        }
        __syncthreads();
        for (int s = 256; s > 0; s >>= 1) {
            if (tid < s)
#pragma unroll
                for (int v = 0; v < 16; v++) sm[tid][v] += sm[tid + s][v];
            __syncthreads();
        }
        if (tid == 0) {
            float ent = 0.0f;
#pragma unroll
            for (int e = 0; e < NE; e++) {
                const float r = sm[0][e] / (float)N_TOK;
                ent += r * logf(r * 8.0f + 1e-9f);
            }
            float tot = 0.0f;
            float SI[NE];
#pragma unroll
            for (int e = 0; e < NE; e++) { SI[e] = sm[0][NE + e] + 1e-9f; tot += SI[e]; }
            float ie = 0.0f;
#pragma unroll
            for (int e = 0; e < NE; e++) {
                const float ip = SI[e] / tot;
                ie -= ip * logf(ip + 1e-9f);
            }
            out_aux[0] = ent - 0.1f * (ie / logf(8.0f));
        }
    }
}

// ================= launch ==========================================================
extern "C" void kernel_launch(void* const* d_in, const int* in_sizes, int n_in,
                              void* d_out, int out_size) {
    const float* x   = (const float*)d_in[0];
    const float* wi1 = (const float*)d_in[1];
    const float* bi1 = (const float*)d_in[2];
    const float* wi2 = (const float*)d_in[3];
    const float* bi2 = (const float*)d_in[4];
    const float* wr1 = (const float*)d_in[5];
    const float* br1 = (const float*)d_in[6];
    const float* wr2 = (const float*)d_in[7];
    const float* br2 = (const float*)d_in[8];
    const float* wu1 = (const float*)d_in[9];
    const float* bu1 = (const float*)d_in[10];
    const float* wu2 = (const float*)d_in[11];
    const float* bu2 = (const float*)d_in[12];

    float* out   = (float*)d_out;
    float* disp  = out;                                   // [4096, 8, 1536]
    float* comb  = disp + (size_t)N_TOK * NE * CAP;       // [4096, 8, 1536]
    float* probs = comb + (size_t)N_TOK * NE * CAP;       // [4096, 8]
    float* aux   = probs + (size_t)N_TOK * NE;            // [1]
    float* imp   = aux + 1;                               // [4096]

    cudaFuncSetAttribute(gemmA_tc, cudaFuncAttributeMaxDynamicSharedMemorySize, SMEM_A_TC);
    cudaFuncSetAttribute(gemmC_tc, cudaFuncAttributeMaxDynamicSharedMemorySize, SMEM_C_TC);

    prep_kernel<<<2560 + 512, 256>>>(x, wi1, wr1, wu1);
    gemmA_tc<<<192, 256, SMEM_A_TC>>>(bi1, (float4*)disp);
    importance_kernel<<<512, 256>>>(wi2, bi2, imp);
    compact_kernel<<<1, 1024>>>();
    gemmC_tc<<<dim3(4, 49), 512, SMEM_C_TC>>>(br1, bu1, (float4*)disp);
    routing_kernel<<<512, 256>>>(wr2, br2, wu2, bu2, probs);
    dispatch_aux_kernel<<<2, 1024>>>(disp, comb, aux);
}

// round 8
// speedup vs baseline: 1.1799x; 1.1799x over previous
#include <cuda_runtime.h>
#include <cstdint>
#include <cstddef>

#define N_TOK 4096
#define HDIM  1024
#define NE    8
#define CAP   1536

// ---------------- scratch (static device globals: no allocation) ----------------
__device__ float g_hi[(size_t)N_TOK * 512];    // importance hidden
__device__ float g_hr[(size_t)N_TOK * 1024];   // selected-router hidden
__device__ float g_p0[N_TOK], g_p1[N_TOK];
__device__ int   g_e0[N_TOK], g_e1[N_TOK];
__device__ unsigned char g_mask[N_TOK];
__device__ int   g_idx_i[N_TOK], g_idx_u[N_TOK];
__device__ int   g_cnt[2];
__device__ float g_part[512 * 16];

// zeroing split: output region 25,165,824 float4 total
#define ZA_F4 9830400                  // 150 MB zeroed inside gemmA wave
#define ZC_F4 (25165824 - ZA_F4)       // 252 MB zeroed inside gemmC wave

// ---------------- packed f32x2 helpers ----------------
static __device__ __forceinline__ void fma2(unsigned long long& d,
                                            unsigned long long a,
                                            unsigned long long b) {
    asm("fma.rn.f32x2 %0, %1, %2, %0;" : "+l"(d) : "l"(a), "l"(b));
}
static __device__ __forceinline__ unsigned long long pack2(float x, float y) {
    unsigned long long r;
    asm("mov.b64 %0, {%1, %2};" : "=l"(r) : "f"(x), "f"(y));
    return r;
}
static __device__ __forceinline__ float2 unpack2(unsigned long long v) {
    float2 r;
    asm("mov.b64 {%0, %1}, %2;" : "=f"(r.x), "=f"(r.y) : "l"(v));
    return r;
}

// ---------------- gemmA: relu(X@wi1 + bi1) -> g_hi, plus zero-ballast CTAs ---------
// 1D grid 192: bx<128 compute (128x128 tile, BK=8, f32x2 8x8 microtile); else zero.
__global__ __launch_bounds__(256, 2)
void gemmA_kernel(const float* __restrict__ x,
                  const float* __restrict__ wi1, const float* __restrict__ bi1,
                  float4* __restrict__ zero_base) {
    const int bx = blockIdx.x;
    if (bx >= 128) {
        const int z = bx - 128;
        const float4 zz = make_float4(0.f, 0.f, 0.f, 0.f);
        for (size_t i = (size_t)z * 256 + threadIdx.x; i < (size_t)ZA_F4; i += (size_t)64 * 256)
            zero_base[i] = zz;
        return;
    }
    __shared__ __align__(16) float As[2][8][128];
    __shared__ __align__(16) float Bs[2][8][128];

    const int ncol0 = (bx & 3) * 128;     // 4 col tiles
    const int m0    = (bx >> 2) * 128;    // 32 row tiles
    const int tid   = threadIdx.x;
    const int arow = tid >> 1,  acol = (tid & 1) * 4;
    const int brow = tid >> 5,  bcol = (tid & 31) * 4;
    const float* Ap = x   + (size_t)(m0 + arow) * HDIM + acol;
    const float* Bp = wi1 + (size_t)brow * 512 + ncol0 + bcol;
    const int trow = (tid >> 4) * 8;
    const int tcol = (tid & 15) * 8;

    float4 a_ld = *(const float4*)Ap;
    float4 b_ld = *(const float4*)Bp;
    As[0][acol + 0][arow] = a_ld.x;
    As[0][acol + 1][arow] = a_ld.y;
    As[0][acol + 2][arow] = a_ld.z;
    As[0][acol + 3][arow] = a_ld.w;
    *(float4*)&Bs[0][brow][bcol] = b_ld;
    __syncthreads();

    unsigned long long acc[8][4];
#pragma unroll
    for (int i = 0; i < 8; i++)
#pragma unroll
        for (int j = 0; j < 4; j++) acc[i][j] = 0ull;

    for (int kt = 0; kt < 128; kt++) {
        const int cur = kt & 1;
        float4 a_n, b_n;
        if (kt < 127) {
            a_n = *(const float4*)(Ap + (kt + 1) * 8);
            b_n = *(const float4*)(Bp + (size_t)(kt + 1) * 8 * 512);
        }
#pragma unroll
        for (int k = 0; k < 8; k++) {
            float4 a0 = *(const float4*)&As[cur][k][trow];
            float4 a1 = *(const float4*)&As[cur][k][trow + 4];
            ulonglong2 bq0 = *(const ulonglong2*)&Bs[cur][k][tcol];
            ulonglong2 bq1 = *(const ulonglong2*)&Bs[cur][k][tcol + 4];
            const unsigned long long bb0 = bq0.x, bb1 = bq0.y, bb2 = bq1.x, bb3 = bq1.y;
            float av[8] = {a0.x, a0.y, a0.z, a0.w, a1.x, a1.y, a1.z, a1.w};
#pragma unroll
            for (int i = 0; i < 8; i++) {
                unsigned long long aa = pack2(av[i], av[i]);
                fma2(acc[i][0], aa, bb0);
                fma2(acc[i][1], aa, bb1);
                fma2(acc[i][2], aa, bb2);
                fma2(acc[i][3], aa, bb3);
            }
        }
        if (kt < 127) {
            const int nxt = cur ^ 1;
            As[nxt][acol + 0][arow] = a_n.x;
            As[nxt][acol + 1][arow] = a_n.y;
            As[nxt][acol + 2][arow] = a_n.z;
            As[nxt][acol + 3][arow] = a_n.w;
            *(float4*)&Bs[nxt][brow][bcol] = b_n;
            __syncthreads();
        }
    }

#pragma unroll
    for (int i = 0; i < 8; i++) {
        float* hr = g_hi + (size_t)(m0 + trow + i) * 512 + ncol0 + tcol;
#pragma unroll
        for (int j = 0; j < 4; j++) {
            float2 v = unpack2(acc[i][j]);
            v.x = fmaxf(v.x + bi1[ncol0 + tcol + 2 * j],     0.0f);
            v.y = fmaxf(v.y + bi1[ncol0 + tcol + 2 * j + 1], 0.0f);
            *(float2*)(hr + 2 * j) = v;
        }
    }
}

// ---------------- importance score + mask (warp per token) -------------------------
__global__ void importance_kernel(const float* __restrict__ wi2, const float* __restrict__ bi2,
                                  float* __restrict__ out_imp) {
    const int gt   = (blockIdx.x * blockDim.x + threadIdx.x) >> 5;
    const int lane = threadIdx.x & 31;
    if (gt >= N_TOK) return;
    const float* hr = g_hi + (size_t)gt * 512;
    float z = 0.0f;
    for (int j = lane; j < 512; j += 32) z = fmaf(hr[j], wi2[j], z);
#pragma unroll
    for (int off = 16; off > 0; off >>= 1) z += __shfl_xor_sync(0xffffffffu, z, off);
    if (lane == 0) {
        z += bi2[0];
        const float sig = 1.0f / (1.0f + expf(-z));
        out_imp[gt] = sig;
        g_mask[gt] = (sig > 0.5f) ? 1 : 0;
    }
}

// ---------------- compaction: ordered token lists per branch -----------------------
__global__ void compact_kernel() {
    __shared__ int wcnt_i[32], wcnt_u[32], wpre_i[32], wpre_u[32];
    __shared__ int base_i, base_u;
    const int tid = threadIdx.x, lane = tid & 31, warp = tid >> 5;
    if (tid == 0) { base_i = 0; base_u = 0; }
    __syncthreads();
    for (int c = 0; c < 4; c++) {
        const int t = c * 1024 + tid;
        const int m = g_mask[t];
        const unsigned bi = __ballot_sync(0xffffffffu, m);
        const unsigned lt = (1u << lane) - 1u;
        if (lane == 0) { wcnt_i[warp] = __popc(bi); wcnt_u[warp] = 32 - __popc(bi); }
        __syncthreads();
        if (tid == 0) {
            int si = base_i, su = base_u;
            for (int w = 0; w < 32; w++) {
                wpre_i[w] = si; si += wcnt_i[w];
                wpre_u[w] = su; su += wcnt_u[w];
            }
            base_i = si; base_u = su;
        }
        __syncthreads();
        if (m) g_idx_i[wpre_i[warp] + __popc(bi & lt)] = t;
        else   g_idx_u[wpre_u[warp] + __popc(~bi & lt)] = t;
        __syncthreads();
    }
    if (tid == 0) { g_cnt[0] = base_i; g_cnt[1] = base_u; }
}

// ---------------- gemmC: gathered router GEMM + zero-ballast CTAs ------------------
// 1D grid of exactly 296 CTAs (one full wave at occ=2): bid < 8*nc compute
// (col tile = bid&7, row tile = bid>>3 over [imp list | unimp list]); rest zero.
__global__ __launch_bounds__(256, 2)
void gemmC_kernel(const float* __restrict__ x,
                  const float* __restrict__ wr1, const float* __restrict__ br1,
                  const float* __restrict__ wu1, const float* __restrict__ bu1,
                  float4* __restrict__ zero_base) {
    const int ci = g_cnt[0], cu = g_cnt[1];
    const int ti = (ci + 127) >> 7;
    const int tu = (cu + 127) >> 7;
    const int nc = ti + tu;                       // 32 or 33 row tiles
    const int bid = blockIdx.x;
    if (bid >= 8 * nc) {
        // zero role: nz = 296 - 8*nc CTAs (>= 32), all wave 1
        const int z  = bid - 8 * nc;
        const int nz = 296 - 8 * nc;
        const float4 zz = make_float4(0.f, 0.f, 0.f, 0.f);
        for (size_t i = (size_t)z * 256 + threadIdx.x; i < (size_t)ZC_F4; i += (size_t)nz * 256)
            zero_base[(size_t)ZA_F4 + i] = zz;
        return;
    }
    const int rt = bid >> 3;
    const float* W; const float* bias; const int* list; int base, cnt;
    if (rt < ti) { W = wr1; bias = br1; list = g_idx_i; base = rt << 7;        cnt = ci; }
    else         { W = wu1; bias = bu1; list = g_idx_u; base = (rt - ti) << 7; cnt = cu; }

    __shared__ __align__(16) float As[2][8][128];
    __shared__ __align__(16) float Bs[2][8][128];
    __shared__ int s_tok[128];

    const int ncol0 = (bid & 7) * 128;
    const int tid   = threadIdx.x;
    if (tid < 128) {
        const int r = base + tid;
        s_tok[tid] = (r < cnt) ? list[r] : -1;
    }
    __syncthreads();

    const int arow = tid >> 1,  acol = (tid & 1) * 4;
    const int brow = tid >> 5,  bcol = (tid & 31) * 4;
    const int tokA = s_tok[arow];
    const float* Ap = x + (size_t)(tokA < 0 ? 0 : tokA) * HDIM + acol;
    const float* Bp = W + (size_t)brow * 1024 + ncol0 + bcol;
    const int trow = (tid >> 4) * 8;
    const int tcol = (tid & 15) * 8;

    float4 a_ld = *(const float4*)Ap;
    float4 b_ld = *(const float4*)Bp;
    As[0][acol + 0][arow] = a_ld.x;
    As[0][acol + 1][arow] = a_ld.y;
    As[0][acol + 2][arow] = a_ld.z;
    As[0][acol + 3][arow] = a_ld.w;
    *(float4*)&Bs[0][brow][bcol] = b_ld;
    __syncthreads();

    unsigned long long acc[8][4];
#pragma unroll
    for (int i = 0; i < 8; i++)
#pragma unroll
        for (int j = 0; j < 4; j++) acc[i][j] = 0ull;

    for (int kt = 0; kt < 128; kt++) {
        const int cur = kt & 1;
        float4 a_n, b_n;
        if (kt < 127) {
            a_n = *(const float4*)(Ap + (kt + 1) * 8);
            b_n = *(const float4*)(Bp + (size_t)(kt + 1) * 8 * 1024);
        }
#pragma unroll
        for (int k = 0; k < 8; k++) {
            float4 a0 = *(const float4*)&As[cur][k][trow];
            float4 a1 = *(const float4*)&As[cur][k][trow + 4];
            ulonglong2 bq0 = *(const ulonglong2*)&Bs[cur][k][tcol];
            ulonglong2 bq1 = *(const ulonglong2*)&Bs[cur][k][tcol + 4];
            const unsigned long long bb0 = bq0.x, bb1 = bq0.y, bb2 = bq1.x, bb3 = bq1.y;
            float av[8] = {a0.x, a0.y, a0.z, a0.w, a1.x, a1.y, a1.z, a1.w};
#pragma unroll
            for (int i = 0; i < 8; i++) {
                unsigned long long aa = pack2(av[i], av[i]);
                fma2(acc[i][0], aa, bb0);
                fma2(acc[i][1], aa, bb1);
                fma2(acc[i][2], aa, bb2);
                fma2(acc[i][3], aa, bb3);
            }
        }
        if (kt < 127) {
            const int nxt = cur ^ 1;
            As[nxt][acol + 0][arow] = a_n.x;
            As[nxt][acol + 1][arow] = a_n.y;
            As[nxt][acol + 2][arow] = a_n.z;
            As[nxt][acol + 3][arow] = a_n.w;
            *(float4*)&Bs[nxt][brow][bcol] = b_n;
            __syncthreads();
        }
    }

#pragma unroll
    for (int i = 0; i < 8; i++) {
        const int tok = s_tok[trow + i];
        if (tok < 0) continue;
        float* hr = g_hr + (size_t)tok * 1024 + ncol0 + tcol;
#pragma unroll
        for (int j = 0; j < 4; j++) {
            float2 v = unpack2(acc[i][j]);
            v.x = fmaxf(v.x + bias[ncol0 + tcol + 2 * j],     0.0f);
            v.y = fmaxf(v.y + bias[ncol0 + tcol + 2 * j + 1], 0.0f);
            *(float2*)(hr + 2 * j) = v;
        }
    }
}

// ---------------- routing: second layer + softmax + top-2 + aux partials -----------
__global__ void routing_kernel(const float* __restrict__ wr2, const float* __restrict__ br2,
                               const float* __restrict__ wu2, const float* __restrict__ bu2,
                               float* __restrict__ out_probs) {
    __shared__ float s_aux[8][16];
    const int gt   = (blockIdx.x * blockDim.x + threadIdx.x) >> 5;
    const int lane = threadIdx.x & 31;
    const int warp = threadIdx.x >> 5;
    if (gt < N_TOK) {
        const bool m = g_mask[gt] != 0;
        const float* hs = g_hr + (size_t)gt * 1024;
        const float* W2 = m ? wr2 : wu2;
        const float* b2 = m ? br2 : bu2;
        float acc[NE];
#pragma unroll
        for (int e = 0; e < NE; e++) acc[e] = 0.0f;
        for (int j = lane; j < 1024; j += 32) {
            const float hv = hs[j];
            float4 w0 = *(const float4*)(W2 + (size_t)j * 8);
            float4 w1 = *(const float4*)(W2 + (size_t)j * 8 + 4);
            acc[0] = fmaf(hv, w0.x, acc[0]);
            acc[1] = fmaf(hv, w0.y, acc[1]);
            acc[2] = fmaf(hv, w0.z, acc[2]);
            acc[3] = fmaf(hv, w0.w, acc[3]);
            acc[4] = fmaf(hv, w1.x, acc[4]);
            acc[5] = fmaf(hv, w1.y, acc[5]);
            acc[6] = fmaf(hv, w1.z, acc[6]);
            acc[7] = fmaf(hv, w1.w, acc[7]);
        }
#pragma unroll
        for (int off = 16; off > 0; off >>= 1)
#pragma unroll
            for (int e = 0; e < NE; e++) acc[e] += __shfl_xor_sync(0xffffffffu, acc[e], off);

        if (lane == 0) {
            float l[NE], pr[NE];
            float mx = -1e30f;
#pragma unroll
            for (int e = 0; e < NE; e++) { l[e] = acc[e] + b2[e]; mx = fmaxf(mx, l[e]); }
            float sum = 0.0f;
#pragma unroll
            for (int e = 0; e < NE; e++) { pr[e] = expf(l[e] - mx); sum += pr[e]; }
            const float inv = 1.0f / sum;
            const float mf = m ? 1.0f : 0.0f;
#pragma unroll
            for (int e = 0; e < NE; e++) {
                pr[e] *= inv;
                out_probs[(size_t)gt * NE + e] = pr[e];
                s_aux[warp][e]      = pr[e];
                s_aux[warp][NE + e] = pr[e] * mf;
            }
            int e0 = 0; float p0v = pr[0];
#pragma unroll
            for (int e = 1; e < NE; e++) if (pr[e] > p0v) { p0v = pr[e]; e0 = e; }
            int e1 = -1; float p1v = -1.0f;
#pragma unroll
            for (int e = 0; e < NE; e++) if (e != e0 && pr[e] > p1v) { p1v = pr[e]; e1 = e; }
            const float sn = p0v + p1v;
            g_e0[gt] = e0; g_e1[gt] = e1;
            g_p0[gt] = p0v / sn; g_p1[gt] = p1v / sn;
        }
    }
    __syncthreads();
    if (threadIdx.x < 16) {
        float s = 0.0f;
        for (int w = 0; w < 8; w++) s += s_aux[w][threadIdx.x];
        g_part[(size_t)blockIdx.x * 16 + threadIdx.x] = s;
    }
}

// ---------------- dispatch (block 0) + aux loss (block 1), merged ------------------
__global__ void dispatch_aux_kernel(float* __restrict__ disp, float* __restrict__ comb,
                                    float* __restrict__ out_aux) {
    const int tid = threadIdx.x;
    if (blockIdx.x == 0) {
        __shared__ int base[NE];
        __shared__ int whist[32][NE];
        __shared__ int wpref[32][NE];
        const int lane = tid & 31, warp = tid >> 5;
        if (tid < NE) base[tid] = 0;
        __syncthreads();
        for (int chunk = 0; chunk < 8; chunk++) {
            const int i = chunk * 1024 + tid;
            const int k = i >> 12;
            const int t = i & (N_TOK - 1);
            const int e   = (k == 0) ? g_e0[t] : g_e1[t];
            const float p = (k == 0) ? g_p0[t] : g_p1[t];

            if (lane < NE) whist[warp][lane] = 0;
            __syncwarp();
            const unsigned mm  = __match_any_sync(0xffffffffu, e);
            const unsigned blo = mm & ((1u << lane) - 1u);
            const int rank = __popc(blo);
            if (blo == 0u) whist[warp][e] = __popc(mm);
            __syncthreads();

            if (tid < NE) {
                int s = base[tid];
                for (int w = 0; w < 32; w++) { wpref[w][tid] = s; s += whist[w][tid]; }
                base[tid] = s;
            }
            __syncthreads();

            const int pos = wpref[warp][e] + rank;
            if (pos < CAP) {
                const size_t idx = ((size_t)t * NE + e) * CAP + pos;
                disp[idx] = 1.0f;
                comb[idx] = p;
            }
            __syncthreads();
        }
    } else {
        __shared__ float sm[512][16];
        if (tid < 512) {
#pragma unroll
            for (int v = 0; v < 16; v++) sm[tid][v] = g_part[(size_t)tid * 16 + v];
        }
        __syncthreads();
        for (int s = 256; s > 0; s >>= 1) {
            if (tid < s)
#pragma unroll
                for (int v = 0; v < 16; v++) sm[tid][v] += sm[tid + s][v];
            __syncthreads();
        }
        if (tid == 0) {
            float ent = 0.0f;
#pragma unroll
            for (int e = 0; e < NE; e++) {
                const float r = sm[0][e] / (float)N_TOK;
                ent += r * logf(r * 8.0f + 1e-9f);
            }
            float tot = 0.0f;
            float SI[NE];
#pragma unroll
            for (int e = 0; e < NE; e++) { SI[e] = sm[0][NE + e] + 1e-9f; tot += SI[e]; }
            float ie = 0.0f;
#pragma unroll
            for (int e = 0; e < NE; e++) {
                const float ip = SI[e] / tot;
                ie -= ip * logf(ip + 1e-9f);
            }
            out_aux[0] = ent - 0.1f * (ie / logf(8.0f));
        }
    }
}

// ---------------- launch -----------------------------------------------------------
extern "C" void kernel_launch(void* const* d_in, const int* in_sizes, int n_in,
                              void* d_out, int out_size) {
    const float* x   = (const float*)d_in[0];
    const float* wi1 = (const float*)d_in[1];
    const float* bi1 = (const float*)d_in[2];
    const float* wi2 = (const float*)d_in[3];
    const float* bi2 = (const float*)d_in[4];
    const float* wr1 = (const float*)d_in[5];
    const float* br1 = (const float*)d_in[6];
    const float* wr2 = (const float*)d_in[7];
    const float* br2 = (const float*)d_in[8];
    const float* wu1 = (const float*)d_in[9];
    const float* bu1 = (const float*)d_in[10];
    const float* wu2 = (const float*)d_in[11];
    const float* bu2 = (const float*)d_in[12];

    float* out   = (float*)d_out;
    float* disp  = out;                                   // [4096, 8, 1536]
    float* comb  = disp + (size_t)N_TOK * NE * CAP;       // [4096, 8, 1536]
    float* probs = comb + (size_t)N_TOK * NE * CAP;       // [4096, 8]
    float* aux   = probs + (size_t)N_TOK * NE;            // [1]
    float* imp   = aux + 1;                               // [4096]

    gemmA_kernel<<<192, 256>>>(x, wi1, bi1, (float4*)disp);
    importance_kernel<<<512, 256>>>(wi2, bi2, imp);
    compact_kernel<<<1, 1024>>>();
    gemmC_kernel<<<296, 256>>>(x, wr1, br1, wu1, bu1, (float4*)disp);
    routing_kernel<<<512, 256>>>(wr2, br2, wu2, bu2, probs);
    dispatch_aux_kernel<<<2, 1024>>>(disp, comb, aux);
}